// round 12
// baseline (speedup 1.0000x reference)
#include <cuda_runtime.h>
#include <cstdint>

// Problem constants
#define NNODES 1024
#define BB     8
#define FF     128
#define OO     128
#define DDIR   3
#define NB     (NNODES*BB)      // 8192

// ---------------- scratch (static device memory; no allocations) ----------------
__device__ float g_support[DDIR*NNODES*BB*OO];   // [d][n][b][o]
__device__ float g_supT   [DDIR*BB*OO*NNODES];   // [d*8+b][o][n]  (tf32-rounded)
__device__ float g_agg    [DDIR*NNODES*BB*OO];   // [d][n][b][o]
__device__ float g_gi     [DDIR*NNODES*BB*384];
__device__ float g_ght    [NB*512];              // [n*B+b][ gh_r|gh_z|gh_n|t_pre ]
__device__ float g_x      [NB*FF];               // intermediate x after layer 0
__device__ float g_wTr    [2*DDIR*OO*FF];        // W[l,d]^T, tf32-rounded
__device__ float g_whcatr [2*512*128];           // [Whh | Wh^T], tf32-rounded
__device__ float g_wihr   [2*384*128];           // Wih, tf32-rounded
__device__ float g_bcat   [2*512];               // [bhh | Bh] per layer (raw fp32)

// ======================= helpers =======================
__device__ __forceinline__ uint32_t smem_to_u32(const void* p) {
    uint32_t a;
    asm("{ .reg .u64 t; cvta.to.shared.u64 t, %1; cvt.u32.u64 %0, t; }" : "=r"(a) : "l"(p));
    return a;
}
__device__ __forceinline__ void cp_async16(uint32_t dst, const void* src) {
    asm volatile("cp.async.cg.shared.global [%0], [%1], 16;" :: "r"(dst), "l"(src));
}
__device__ __forceinline__ void cp_commit() {
    asm volatile("cp.async.commit_group;" ::: "memory");
}
template<int N>
__device__ __forceinline__ void cp_wait() {
    asm volatile("cp.async.wait_group %0;" :: "n"(N) : "memory");
}

// fp32 -> tf32 round-to-nearest, raw bits
__device__ __forceinline__ uint32_t tf32b(float v) {
    uint32_t u;
    asm("cvt.rna.tf32.f32 %0, %1;" : "=r"(u) : "f"(v));
    return u;
}
__device__ __forceinline__ float tf32f(float v) { return __uint_as_float(tf32b(v)); }

__device__ __forceinline__ void mma_tf32(float* c, const uint32_t* a, const uint32_t* b) {
    asm volatile(
        "mma.sync.aligned.m16n8k8.row.col.f32.tf32.tf32.f32 "
        "{%0,%1,%2,%3}, {%4,%5,%6,%7}, {%8,%9}, {%0,%1,%2,%3};"
        : "+f"(c[0]), "+f"(c[1]), "+f"(c[2]), "+f"(c[3])
        : "r"(a[0]), "r"(a[1]), "r"(a[2]), "r"(a[3]), "r"(b[0]), "r"(b[1]));
}

__device__ __forceinline__ float sigmoidf_(float x) {
    return 0.5f * (1.0f + tanhf(0.5f * x));
}

// ---------------------------------------------------------------------------
// 1x generic GEMM (R11-proven): B PRE-ROUNDED tf32; A rounded at fragment load.
//   C[z][m][n] = sum_k A[z][m][k] * B[z][n][k]  (+ bias[n])
// Block 256 thr = 8 warps (2 x 4), warp tile 64x32, BM=BN=128, BK=16.
// ---------------------------------------------------------------------------
__global__ void __launch_bounds__(256, 2) mma_gemm_1x(
    const float* __restrict__ A, const float* __restrict__ Bm,
    const float* __restrict__ bias, float* __restrict__ C,
    int K, int lda, int ldb, int ldc,
    long aStride, long bStride, int zdiv,
    long cOuter, long cInner, int biasStride)
{
    const int tid   = threadIdx.x;
    const int warp  = tid >> 5;
    const int lane  = tid & 31;
    const int group = lane >> 2;
    const int tig   = lane & 3;
    const int wm    = (warp >> 2) * 64;
    const int wn    = (warp & 3) * 32;
    const int z     = blockIdx.z;

    const long baseA = (long)z*aStride + (long)blockIdx.x*128*lda;
    const long baseB = (long)z*bStride + (long)blockIdx.y*128*ldb;
    const long baseC = (long)(z/zdiv)*cOuter + (long)(z%zdiv)*cInner
                     + (long)blockIdx.x*128*ldc + (long)blockIdx.y*128;

    __shared__ __align__(16) float As[2][128][20];
    __shared__ __align__(16) float Bs[2][128][20];

    float c[4][4][4];
    #pragma unroll
    for (int ma = 0; ma < 4; ma++)
        #pragma unroll
        for (int na = 0; na < 4; na++)
            #pragma unroll
            for (int q = 0; q < 4; q++) c[ma][na][q] = 0.f;

    const int numK = K / 16;
    const int row  = tid >> 2;
    const int kq   = (tid & 3) << 2;

    #pragma unroll
    for (int i = 0; i < 2; i++) {
        int r = row + i*64;
        *(float4*)&As[0][r][kq] = *(const float4*)&A [baseA + (long)r*lda + kq];
        *(float4*)&Bs[0][r][kq] = *(const float4*)&Bm[baseB + (long)r*ldb + kq];
    }
    __syncthreads();

    for (int kt = 0; kt < numK; kt++) {
        const int  cur = kt & 1;
        const bool has = (kt + 1 < numK);
        float4 pa[2], pb[2];
        if (has) {
            const int k0 = (kt + 1) * 16;
            #pragma unroll
            for (int i = 0; i < 2; i++) {
                int r = row + i*64;
                pa[i] = *(const float4*)&A [baseA + (long)r*lda + k0 + kq];
                pb[i] = *(const float4*)&Bm[baseB + (long)r*ldb + k0 + kq];
            }
        }
        #pragma unroll
        for (int ks = 0; ks < 16; ks += 8) {
            uint32_t b[4][2];
            #pragma unroll
            for (int na = 0; na < 4; na++) {
                int n0 = wn + na*8 + group;
                b[na][0] = __float_as_uint(Bs[cur][n0][ks + tig]);      // pre-rounded
                b[na][1] = __float_as_uint(Bs[cur][n0][ks + tig + 4]);
            }
            #pragma unroll
            for (int ma = 0; ma < 4; ma++) {
                int r0 = wm + ma*16 + group;
                uint32_t a[4];
                a[0] = tf32b(As[cur][r0    ][ks + tig]);
                a[1] = tf32b(As[cur][r0 + 8][ks + tig]);
                a[2] = tf32b(As[cur][r0    ][ks + tig + 4]);
                a[3] = tf32b(As[cur][r0 + 8][ks + tig + 4]);
                #pragma unroll
                for (int na = 0; na < 4; na++)
                    mma_tf32(c[ma][na], a, b[na]);
            }
        }
        if (has) {
            const int nxt = cur ^ 1;
            #pragma unroll
            for (int i = 0; i < 2; i++) {
                int r = row + i*64;
                *(float4*)&As[nxt][r][kq] = pa[i];
                *(float4*)&Bs[nxt][r][kq] = pb[i];
            }
            __syncthreads();
        }
    }

    const float* bp = bias ? (bias + (long)z*biasStride + blockIdx.y*128) : nullptr;
    #pragma unroll
    for (int ma = 0; ma < 4; ma++) {
        #pragma unroll
        for (int na = 0; na < 4; na++) {
            int gr = wm + ma*16 + group;
            int gc = wn + na*8 + tig*2;
            float b0 = 0.f, b1 = 0.f;
            if (bp) { b0 = bp[gc]; b1 = bp[gc + 1]; }
            long p0 = baseC + (long)gr*ldc + gc;
            *(float2*)&C[p0]         = make_float2(c[ma][na][0] + b0, c[ma][na][1] + b1);
            *(float2*)&C[p0 + 8*ldc] = make_float2(c[ma][na][2] + b0, c[ma][na][3] + b1);
        }
    }
}

// ---------------------------------------------------------------------------
// agg v3 (1x tf32): agg[db] = adj[db] (1024x1024) @ supT[db]^T (128x1024)
// BM=BN=128, BK=32, 3-stage cp.async, single sync/kt, warp tile 64x32.
// grid (8 mtiles, 24 db), block 256, occ 2 (2 x 110.6KB smem per SM).
// Numerics bit-identical to R7 agg (same k-order, RN rounding of A; B pre-rounded).
// ---------------------------------------------------------------------------
#define AG3_STRIDE 36
#define AG3_STAGE  (128*AG3_STRIDE)                 // floats per operand stage (4608)
#define AG3_SMEM_BYTES (3*2*AG3_STAGE*4)            // 110592

__device__ __forceinline__ void ag3_issue(
    uint32_t asBase, uint32_t bsBase,
    const float* Abase, const float* Bbase,
    int row, int seg, int buf, int kt)
{
    const int col = kt*32 + seg*16;
    uint32_t da = asBase + (uint32_t)(buf*AG3_STAGE + row*AG3_STRIDE + seg*16)*4;
    uint32_t db = bsBase + (uint32_t)(buf*AG3_STAGE + row*AG3_STRIDE + seg*16)*4;
    const float* sa = Abase + (size_t)row*1024 + col;
    const float* sb = Bbase + (size_t)row*1024 + col;
    #pragma unroll
    for (int q = 0; q < 4; q++) {
        cp_async16(da + q*16, sa + q*4);
        cp_async16(db + q*16, sb + q*4);
    }
    cp_commit();
}

__global__ void __launch_bounds__(256, 2)
agg_mma_k(const float* __restrict__ adj, const float* __restrict__ supT,
          float* __restrict__ agg)
{
    extern __shared__ __align__(16) float sm[];
    float* As = sm;                   // [3][128][36]
    float* Bs = sm + 3*AG3_STAGE;     // [3][128][36]
    const uint32_t asBase = smem_to_u32(As);
    const uint32_t bsBase = smem_to_u32(Bs);

    const int tid   = threadIdx.x;
    const int warp  = tid >> 5;
    const int lane  = tid & 31;
    const int group = lane >> 2;
    const int tig   = lane & 3;
    const int wm    = (warp >> 2) * 64;
    const int wn    = (warp & 3) * 32;
    const int mt    = blockIdx.x;
    const int db    = blockIdx.y;

    const float* Abase = adj  + (size_t)db*1048576 + (size_t)mt*131072;  // [128 x 1024]
    const float* Bbase = supT + (size_t)db*131072;                       // [128 x 1024]
    const int row = tid >> 1;       // 0..127
    const int seg = tid & 1;        // 16-float half of the 32-float chunk

    float c[4][4][4];
    #pragma unroll
    for (int ma = 0; ma < 4; ma++)
        #pragma unroll
        for (int na = 0; na < 4; na++)
            #pragma unroll
            for (int q = 0; q < 4; q++) c[ma][na][q] = 0.f;

    // prologue: stages for kt = 0, 1
    ag3_issue(asBase, bsBase, Abase, Bbase, row, seg, 0, 0);
    ag3_issue(asBase, bsBase, Abase, Bbase, row, seg, 1, 1);

    for (int kt = 0; kt < 32; kt++) {
        cp_wait<1>();          // kt's stage complete (kt+1 may be in flight)
        __syncthreads();
        const int buf = kt % 3;
        const float* Asb = As + buf*AG3_STAGE;
        const float* Bsb = Bs + buf*AG3_STAGE;
        #pragma unroll
        for (int ks = 0; ks < 32; ks += 8) {
            uint32_t b[4][2];
            #pragma unroll
            for (int na = 0; na < 4; na++) {
                int n0 = wn + na*8 + group;
                b[na][0] = __float_as_uint(Bsb[n0*AG3_STRIDE + ks + tig]);      // pre-rounded
                b[na][1] = __float_as_uint(Bsb[n0*AG3_STRIDE + ks + tig + 4]);
            }
            #pragma unroll
            for (int ma = 0; ma < 4; ma++) {
                int r0 = wm + ma*16 + group;
                uint32_t a[4];
                a[0] = tf32b(Asb[r0*AG3_STRIDE + ks + tig]);
                a[1] = tf32b(Asb[(r0+8)*AG3_STRIDE + ks + tig]);
                a[2] = tf32b(Asb[r0*AG3_STRIDE + ks + tig + 4]);
                a[3] = tf32b(Asb[(r0+8)*AG3_STRIDE + ks + tig + 4]);
                #pragma unroll
                for (int na = 0; na < 4; na++)
                    mma_tf32(c[ma][na], a, b[na]);
            }
        }
        if (kt + 2 < 32)
            ag3_issue(asBase, bsBase, Abase, Bbase, row, seg, (kt + 2) % 3, kt + 2);
    }

    // epilogue: agg[d][n][b][o]
    const int d  = db >> 3;
    const int bb = db & 7;
    #pragma unroll
    for (int ma = 0; ma < 4; ma++) {
        #pragma unroll
        for (int na = 0; na < 4; na++) {
            int n0 = mt*128 + wm + ma*16 + group;
            int o  = wn + na*8 + tig*2;
            size_t base = ((size_t)(d*1024 + n0)*8 + bb)*128 + o;
            *(float2*)&agg[base]        = make_float2(c[ma][na][0], c[ma][na][1]);
            *(float2*)&agg[base + 8192] = make_float2(c[ma][na][2], c[ma][na][3]);
        }
    }
}

// ---------------- support transpose: [d][n][b][o] -> [db][o][n], tf32-rounded ----------------
__global__ void transpose_support(const float* __restrict__ sup, float* __restrict__ supT)
{
    __shared__ float t[32][33];
    int db = blockIdx.z;
    int n0 = blockIdx.x * 32, o0 = blockIdx.y * 32;
    int d = db >> 3, b = db & 7;
    int tx = threadIdx.x, ty = threadIdx.y;   // 32 x 8
    #pragma unroll
    for (int j = 0; j < 4; j++) {
        int n = n0 + ty + j*8;
        t[ty + j*8][tx] = sup[((size_t)(d*1024 + n)*8 + b)*128 + o0 + tx];
    }
    __syncthreads();
    #pragma unroll
    for (int j = 0; j < 4; j++) {
        int o = o0 + ty + j*8;
        supT[((size_t)db*128 + o)*1024 + n0 + tx] = tf32f(t[tx][ty + j*8]);
    }
}

// ---------------- one-time weight prep (all B operands pre-rounded to tf32) ----------------
__global__ void prep_weights(const float* __restrict__ W,   const float* __restrict__ Whh,
                             const float* __restrict__ Wh,  const float* __restrict__ Wih,
                             const float* __restrict__ bhh, const float* __restrict__ Bh,
                             float* __restrict__ wTr, float* __restrict__ whcatr,
                             float* __restrict__ wihr, float* __restrict__ bcat)
{
    int idx = blockIdx.x*blockDim.x + threadIdx.x;   // < 131072
    if (idx < 2*DDIR*128*128) {                      // wTr[l][d][o][f] = tf32(W[l][d][f][o])
        int ld = idx / 16384;
        int rem = idx & 16383;
        int o = rem >> 7, f = rem & 127;
        wTr[idx] = tf32f(W[((long)ld*128 + f)*128 + o]);
    }
    if (idx < 2*512*128) {                           // whcatr[l][n][k], rounded
        int l = idx >> 16;
        int rem = idx & 65535;
        int n = rem >> 7, k = rem & 127;
        float v = (n < 384) ? Whh[((long)l*384 + n)*128 + k]
                            : Wh[((long)l*128 + k)*128 + (n - 384)];
        whcatr[idx] = tf32f(v);
    }
    if (idx < 2*384*128) {                           // wihr = tf32(Wih), native layout
        wihr[idx] = tf32f(Wih[idx]);
    }
    if (idx < 2*512) {
        int l = idx >> 9, j = idx & 511;
        bcat[idx] = (j < 384) ? bhh[l*384 + j] : Bh[l*128 + (j-384)];
    }
}

// ---------------- fused GRU gates + d-sum + relu + highway ----------------
__global__ void gru_highway(const float* __restrict__ xin, const float* __restrict__ ght,
                            const float* __restrict__ gi, float* __restrict__ xout)
{
    int idx = blockIdx.x*blockDim.x + threadIdx.x;
    int o = idx & 127;
    int r = idx >> 7;
    float h = xin[idx];
    const float* g = ght + (long)r*512;
    float ghr = g[o], ghz = g[128+o], ghn = g[256+o];
    float t = fmaxf(g[384+o], 0.0f);
    float acc = 0.0f;
    #pragma unroll
    for (int d = 0; d < 3; d++) {
        const float* gp = gi + ((long)(d*8192 + r))*384;
        float rr = sigmoidf_(gp[o]       + ghr);
        float zz = sigmoidf_(gp[128 + o] + ghz);
        float nn = tanhf    (gp[256 + o] + rr*ghn);
        acc += (1.0f - zz)*nn + zz*h;
    }
    float outv = fmaxf(acc, 0.0f);
    xout[idx] = outv*t + h*(1.0f - t);
}

// ---------------------------------------------------------------------------
extern "C" void kernel_launch(void* const* d_in, const int* in_sizes, int n_in,
                              void* d_out, int out_size)
{
    const float* inputs = (const float*)d_in[0];
    const float* adj    = (const float*)d_in[1];
    const float* W      = (const float*)d_in[2];
    const float* Bc     = (const float*)d_in[3];
    const float* Wh     = (const float*)d_in[4];
    const float* Bh     = (const float*)d_in[5];
    const float* Wih    = (const float*)d_in[6];
    const float* Whh    = (const float*)d_in[7];
    const float* bih    = (const float*)d_in[8];
    const float* bhh    = (const float*)d_in[9];
    float* out = (float*)d_out;
    (void)in_sizes; (void)n_in; (void)out_size;

    float *support, *supT, *agg, *gi, *ght, *xmid, *wTr, *whcatr, *wihr, *bcat;
    cudaGetSymbolAddress((void**)&support, g_support);
    cudaGetSymbolAddress((void**)&supT,    g_supT);
    cudaGetSymbolAddress((void**)&agg,     g_agg);
    cudaGetSymbolAddress((void**)&gi,      g_gi);
    cudaGetSymbolAddress((void**)&ght,     g_ght);
    cudaGetSymbolAddress((void**)&xmid,    g_x);
    cudaGetSymbolAddress((void**)&wTr,     g_wTr);
    cudaGetSymbolAddress((void**)&whcatr,  g_whcatr);
    cudaGetSymbolAddress((void**)&wihr,    g_wihr);
    cudaGetSymbolAddress((void**)&bcat,    g_bcat);

    cudaFuncSetAttribute(agg_mma_k, cudaFuncAttributeMaxDynamicSharedMemorySize,
                         AG3_SMEM_BYTES);

    prep_weights<<<512, 256>>>(W, Whh, Wh, Wih, bhh, Bh, wTr, whcatr, wihr, bcat);

    for (int l = 0; l < 2; l++) {
        const float* xi = (l == 0) ? inputs : xmid;
        float*       xo = (l == 1) ? out    : xmid;

        // support = x @ W^T + Bc   (1x: B pre-rounded, A rounded at frag)
        mma_gemm_1x<<<dim3(64,1,3), 256>>>(
            xi, wTr + (long)l*DDIR*16384, Bc + l*DDIR*128, support,
            128, 128, 128, 128,
            0L, 16384L, 1,
            (long)NNODES*BB*OO, 0L, 128);

        // supT = transpose, pre-rounded to tf32 (B operand of agg)
        transpose_support<<<dim3(32,4,24), dim3(32,8)>>>(support, supT);

        // agg = adj @ support   (1x tf32, BK=32 3-stage cp.async, occ 2)
        agg_mma_k<<<dim3(8,24), 256, AG3_SMEM_BYTES>>>(adj, supT, agg);

        // gi = agg @ Wih^T + bih   (1x)
        mma_gemm_1x<<<dim3(192,3,1), 256>>>(
            agg, wihr + (long)l*384*128, bih + l*384, gi,
            128, 128, 128, 384,
            0L, 0L, 1, 0L, 0L, 0);

        // ght = x @ [Whh | Wh^T]^T + [bhh | Bh]   (1x)
        mma_gemm_1x<<<dim3(64,4,1), 256>>>(
            xi, whcatr + (long)l*512*128, bcat + l*512, ght,
            128, 128, 128, 512,
            0L, 0L, 1, 0L, 0L, 0);

        gru_highway<<<4096, 256>>>(xi, ght, gi, xo);
    }
}

// round 16
// speedup vs baseline: 1.6495x; 1.6495x over previous
#include <cuda_runtime.h>
#include <cstdint>

// Problem constants
#define NNODES 1024
#define BB     8
#define FF     128
#define OO     128
#define DDIR   3
#define NB     (NNODES*BB)      // 8192

// ---------------- scratch (static device memory; no allocations) ----------------
__device__ float g_support[DDIR*NNODES*BB*OO];   // [d][n][b][o]
__device__ float g_supT   [DDIR*BB*OO*NNODES];   // [d*8+b][o][n]  (tf32-rounded)
__device__ float g_agg    [DDIR*NNODES*BB*OO];   // [d][n][b][o]
__device__ float g_gi     [DDIR*NNODES*BB*384];
__device__ float g_ght    [NB*512];              // [n*B+b][ gh_r|gh_z|gh_n|t_pre ]
__device__ float g_x      [NB*FF];               // intermediate x after layer 0
__device__ float g_wTr    [2*DDIR*OO*FF];        // W[l,d]^T, tf32-rounded
__device__ float g_whcatr [2*512*128];           // [Whh | Wh^T], tf32-rounded
__device__ float g_wihr   [2*384*128];           // Wih, tf32-rounded
__device__ float g_bcat   [2*512];               // [bhh | Bh] per layer (raw fp32)

// ======================= helpers =======================
__device__ __forceinline__ uint32_t smem_to_u32(const void* p) {
    uint32_t a;
    asm("{ .reg .u64 t; cvta.to.shared.u64 t, %1; cvt.u32.u64 %0, t; }" : "=r"(a) : "l"(p));
    return a;
}
__device__ __forceinline__ void cp_async16(uint32_t dst, const void* src) {
    asm volatile("cp.async.cg.shared.global [%0], [%1], 16;" :: "r"(dst), "l"(src));
}
__device__ __forceinline__ void cp_commit() {
    asm volatile("cp.async.commit_group;" ::: "memory");
}
template<int N>
__device__ __forceinline__ void cp_wait() {
    asm volatile("cp.async.wait_group %0;" :: "n"(N) : "memory");
}

// fp32 -> tf32 round-to-nearest, raw bits
__device__ __forceinline__ uint32_t tf32b(float v) {
    uint32_t u;
    asm("cvt.rna.tf32.f32 %0, %1;" : "=r"(u) : "f"(v));
    return u;
}
__device__ __forceinline__ float tf32f(float v) { return __uint_as_float(tf32b(v)); }

__device__ __forceinline__ void mma_tf32(float* c, const uint32_t* a, const uint32_t* b) {
    asm volatile(
        "mma.sync.aligned.m16n8k8.row.col.f32.tf32.tf32.f32 "
        "{%0,%1,%2,%3}, {%4,%5,%6,%7}, {%8,%9}, {%0,%1,%2,%3};"
        : "+f"(c[0]), "+f"(c[1]), "+f"(c[2]), "+f"(c[3])
        : "r"(a[0]), "r"(a[1]), "r"(a[2]), "r"(a[3]), "r"(b[0]), "r"(b[1]));
}

__device__ __forceinline__ float sigmoidf_(float x) {
    return 0.5f * (1.0f + tanhf(0.5f * x));
}

// ---------------------------------------------------------------------------
// 1x generic GEMM (R12-proven): B PRE-ROUNDED tf32; A rounded at fragment load.
//   C[z][m][n] = sum_k A[z][m][k] * B[z][n][k]  (+ bias[n])
// Block 256 thr = 8 warps (2 x 4), warp tile 64x32, BM=BN=128, BK=16.
// ---------------------------------------------------------------------------
__global__ void __launch_bounds__(256, 2) mma_gemm_1x(
    const float* __restrict__ A, const float* __restrict__ Bm,
    const float* __restrict__ bias, float* __restrict__ C,
    int K, int lda, int ldb, int ldc,
    long aStride, long bStride, int zdiv,
    long cOuter, long cInner, int biasStride)
{
    const int tid   = threadIdx.x;
    const int warp  = tid >> 5;
    const int lane  = tid & 31;
    const int group = lane >> 2;
    const int tig   = lane & 3;
    const int wm    = (warp >> 2) * 64;
    const int wn    = (warp & 3) * 32;
    const int z     = blockIdx.z;

    const long baseA = (long)z*aStride + (long)blockIdx.x*128*lda;
    const long baseB = (long)z*bStride + (long)blockIdx.y*128*ldb;
    const long baseC = (long)(z/zdiv)*cOuter + (long)(z%zdiv)*cInner
                     + (long)blockIdx.x*128*ldc + (long)blockIdx.y*128;

    __shared__ __align__(16) float As[2][128][20];
    __shared__ __align__(16) float Bs[2][128][20];

    float c[4][4][4];
    #pragma unroll
    for (int ma = 0; ma < 4; ma++)
        #pragma unroll
        for (int na = 0; na < 4; na++)
            #pragma unroll
            for (int q = 0; q < 4; q++) c[ma][na][q] = 0.f;

    const int numK = K / 16;
    const int row  = tid >> 2;
    const int kq   = (tid & 3) << 2;

    #pragma unroll
    for (int i = 0; i < 2; i++) {
        int r = row + i*64;
        *(float4*)&As[0][r][kq] = *(const float4*)&A [baseA + (long)r*lda + kq];
        *(float4*)&Bs[0][r][kq] = *(const float4*)&Bm[baseB + (long)r*ldb + kq];
    }
    __syncthreads();

    for (int kt = 0; kt < numK; kt++) {
        const int  cur = kt & 1;
        const bool has = (kt + 1 < numK);
        float4 pa[2], pb[2];
        if (has) {
            const int k0 = (kt + 1) * 16;
            #pragma unroll
            for (int i = 0; i < 2; i++) {
                int r = row + i*64;
                pa[i] = *(const float4*)&A [baseA + (long)r*lda + k0 + kq];
                pb[i] = *(const float4*)&Bm[baseB + (long)r*ldb + k0 + kq];
            }
        }
        #pragma unroll
        for (int ks = 0; ks < 16; ks += 8) {
            uint32_t b[4][2];
            #pragma unroll
            for (int na = 0; na < 4; na++) {
                int n0 = wn + na*8 + group;
                b[na][0] = __float_as_uint(Bs[cur][n0][ks + tig]);      // pre-rounded
                b[na][1] = __float_as_uint(Bs[cur][n0][ks + tig + 4]);
            }
            #pragma unroll
            for (int ma = 0; ma < 4; ma++) {
                int r0 = wm + ma*16 + group;
                uint32_t a[4];
                a[0] = tf32b(As[cur][r0    ][ks + tig]);
                a[1] = tf32b(As[cur][r0 + 8][ks + tig]);
                a[2] = tf32b(As[cur][r0    ][ks + tig + 4]);
                a[3] = tf32b(As[cur][r0 + 8][ks + tig + 4]);
                #pragma unroll
                for (int na = 0; na < 4; na++)
                    mma_tf32(c[ma][na], a, b[na]);
            }
        }
        if (has) {
            const int nxt = cur ^ 1;
            #pragma unroll
            for (int i = 0; i < 2; i++) {
                int r = row + i*64;
                *(float4*)&As[nxt][r][kq] = pa[i];
                *(float4*)&Bs[nxt][r][kq] = pb[i];
            }
            __syncthreads();
        }
    }

    const float* bp = bias ? (bias + (long)z*biasStride + blockIdx.y*128) : nullptr;
    #pragma unroll
    for (int ma = 0; ma < 4; ma++) {
        #pragma unroll
        for (int na = 0; na < 4; na++) {
            int gr = wm + ma*16 + group;
            int gc = wn + na*8 + tig*2;
            float b0 = 0.f, b1 = 0.f;
            if (bp) { b0 = bp[gc]; b1 = bp[gc + 1]; }
            long p0 = baseC + (long)gr*ldc + gc;
            *(float2*)&C[p0]         = make_float2(c[ma][na][0] + b0, c[ma][na][1] + b1);
            *(float2*)&C[p0 + 8*ldc] = make_float2(c[ma][na][2] + b0, c[ma][na][3] + b1);
        }
    }
}

// ---------------------------------------------------------------------------
// agg v4 (1x tf32): agg[db] = adj[db] (1024x1024) @ supT[db]^T (128x1024)
// R7 tile shape (BM=BN=128, BK=16, warp tile 64x32, 256 thr, occ 2) with a
// 4-stage cp.async pipeline (3 kt of prefetch) replacing register double-buffer.
// smem = 4*(128+128)*20*4 = 80 KB -> 2 CTAs/SM. Numerics identical to R7/R12.
// grid (8 mtiles, 24 db).
// ---------------------------------------------------------------------------
#define AG_STAGES  4
#define AG_STRIDE  20
#define AG_STAGEF  (128*AG_STRIDE)                     // floats per operand stage (2560)
#define AG_SMEM_BYTES (AG_STAGES*2*AG_STAGEF*4)        // 81920

__device__ __forceinline__ void ag_issue(
    uint32_t asBase, uint32_t bsBase,
    const float* Abase, const float* Bbase,
    int tid, int buf, int kt)
{
    const int col = kt*16;
    #pragma unroll
    for (int i = 0; i < 2; i++) {
        int idx = tid + i*256;
        int row = idx >> 2;
        int kq  = (idx & 3) << 2;
        uint32_t soff = (uint32_t)(buf*AG_STAGEF + row*AG_STRIDE + kq)*4;
        cp_async16(asBase + soff, Abase + (size_t)row*1024 + col + kq);
        cp_async16(bsBase + soff, Bbase + (size_t)row*1024 + col + kq);
    }
    cp_commit();
}

__global__ void __launch_bounds__(256, 2)
agg_mma_k(const float* __restrict__ adj, const float* __restrict__ supT,
          float* __restrict__ agg)
{
    extern __shared__ __align__(16) float sm[];
    float* As = sm;                        // [4][128][20]
    float* Bs = sm + AG_STAGES*AG_STAGEF;  // [4][128][20]
    const uint32_t asBase = smem_to_u32(As);
    const uint32_t bsBase = smem_to_u32(Bs);

    const int tid   = threadIdx.x;
    const int warp  = tid >> 5;
    const int lane  = tid & 31;
    const int group = lane >> 2;
    const int tig   = lane & 3;
    const int wm    = (warp >> 2) * 64;
    const int wn    = (warp & 3) * 32;
    const int mt    = blockIdx.x;
    const int db    = blockIdx.y;

    const float* Abase = adj  + (size_t)db*1048576 + (size_t)mt*131072;  // [128 x 1024]
    const float* Bbase = supT + (size_t)db*131072;                       // [128 x 1024]

    float c[4][4][4];
    #pragma unroll
    for (int ma = 0; ma < 4; ma++)
        #pragma unroll
        for (int na = 0; na < 4; na++)
            #pragma unroll
            for (int q = 0; q < 4; q++) c[ma][na][q] = 0.f;

    // prologue: prefetch kt = 0,1,2
    #pragma unroll
    for (int s = 0; s < AG_STAGES - 1; s++)
        ag_issue(asBase, bsBase, Abase, Bbase, tid, s, s);

    for (int kt = 0; kt < 64; kt++) {
        cp_wait<AG_STAGES - 2>();     // kt's stage complete (<=2 groups in flight)
        __syncthreads();
        // issue next stage first (overlap issue with compute); stage (kt+3)%4
        // was consumed at kt-1 and all warps passed the sync above -> WAR-safe.
        if (kt + AG_STAGES - 1 < 64)
            ag_issue(asBase, bsBase, Abase, Bbase, tid,
                     (kt + AG_STAGES - 1) & 3, kt + AG_STAGES - 1);
        const int buf = kt & 3;
        const float* Asb = As + buf*AG_STAGEF;
        const float* Bsb = Bs + buf*AG_STAGEF;
        #pragma unroll
        for (int ks = 0; ks < 16; ks += 8) {
            uint32_t b[4][2];
            #pragma unroll
            for (int na = 0; na < 4; na++) {
                int n0 = wn + na*8 + group;
                b[na][0] = __float_as_uint(Bsb[n0*AG_STRIDE + ks + tig]);    // pre-rounded
                b[na][1] = __float_as_uint(Bsb[n0*AG_STRIDE + ks + tig + 4]);
            }
            #pragma unroll
            for (int ma = 0; ma < 4; ma++) {
                int r0 = wm + ma*16 + group;
                uint32_t a[4];
                a[0] = tf32b(Asb[r0*AG_STRIDE + ks + tig]);
                a[1] = tf32b(Asb[(r0+8)*AG_STRIDE + ks + tig]);
                a[2] = tf32b(Asb[r0*AG_STRIDE + ks + tig + 4]);
                a[3] = tf32b(Asb[(r0+8)*AG_STRIDE + ks + tig + 4]);
                #pragma unroll
                for (int na = 0; na < 4; na++)
                    mma_tf32(c[ma][na], a, b[na]);
            }
        }
    }

    // epilogue: agg[d][n][b][o]   (R12-proven mapping)
    const int d  = db >> 3;
    const int bb = db & 7;
    #pragma unroll
    for (int ma = 0; ma < 4; ma++) {
        #pragma unroll
        for (int na = 0; na < 4; na++) {
            int n0 = mt*128 + wm + ma*16 + group;
            int o  = wn + na*8 + tig*2;
            size_t base = ((size_t)(d*1024 + n0)*8 + bb)*128 + o;
            *(float2*)&agg[base]        = make_float2(c[ma][na][0], c[ma][na][1]);
            *(float2*)&agg[base + 8192] = make_float2(c[ma][na][2], c[ma][na][3]);
        }
    }
}

// ---------------- support transpose: [d][n][b][o] -> [db][o][n], tf32-rounded ----------------
__global__ void transpose_support(const float* __restrict__ sup, float* __restrict__ supT)
{
    __shared__ float t[32][33];
    int db = blockIdx.z;
    int n0 = blockIdx.x * 32, o0 = blockIdx.y * 32;
    int d = db >> 3, b = db & 7;
    int tx = threadIdx.x, ty = threadIdx.y;   // 32 x 8
    #pragma unroll
    for (int j = 0; j < 4; j++) {
        int n = n0 + ty + j*8;
        t[ty + j*8][tx] = sup[((size_t)(d*1024 + n)*8 + b)*128 + o0 + tx];
    }
    __syncthreads();
    #pragma unroll
    for (int j = 0; j < 4; j++) {
        int o = o0 + ty + j*8;
        supT[((size_t)db*128 + o)*1024 + n0 + tx] = tf32f(t[tx][ty + j*8]);
    }
}

// ---------------- one-time weight prep (all B operands pre-rounded to tf32) ----------------
__global__ void prep_weights(const float* __restrict__ W,   const float* __restrict__ Whh,
                             const float* __restrict__ Wh,  const float* __restrict__ Wih,
                             const float* __restrict__ bhh, const float* __restrict__ Bh,
                             float* __restrict__ wTr, float* __restrict__ whcatr,
                             float* __restrict__ wihr, float* __restrict__ bcat)
{
    int idx = blockIdx.x*blockDim.x + threadIdx.x;   // < 131072
    if (idx < 2*DDIR*128*128) {                      // wTr[l][d][o][f] = tf32(W[l][d][f][o])
        int ld = idx / 16384;
        int rem = idx & 16383;
        int o = rem >> 7, f = rem & 127;
        wTr[idx] = tf32f(W[((long)ld*128 + f)*128 + o]);
    }
    if (idx < 2*512*128) {                           // whcatr[l][n][k], rounded
        int l = idx >> 16;
        int rem = idx & 65535;
        int n = rem >> 7, k = rem & 127;
        float v = (n < 384) ? Whh[((long)l*384 + n)*128 + k]
                            : Wh[((long)l*128 + k)*128 + (n - 384)];
        whcatr[idx] = tf32f(v);
    }
    if (idx < 2*384*128) {                           // wihr = tf32(Wih), native layout
        wihr[idx] = tf32f(Wih[idx]);
    }
    if (idx < 2*512) {
        int l = idx >> 9, j = idx & 511;
        bcat[idx] = (j < 384) ? bhh[l*384 + j] : Bh[l*128 + (j-384)];
    }
}

// ---------------- fused GRU gates + d-sum + relu + highway ----------------
__global__ void gru_highway(const float* __restrict__ xin, const float* __restrict__ ght,
                            const float* __restrict__ gi, float* __restrict__ xout)
{
    int idx = blockIdx.x*blockDim.x + threadIdx.x;
    int o = idx & 127;
    int r = idx >> 7;
    float h = xin[idx];
    const float* g = ght + (long)r*512;
    float ghr = g[o], ghz = g[128+o], ghn = g[256+o];
    float t = fmaxf(g[384+o], 0.0f);
    float acc = 0.0f;
    #pragma unroll
    for (int d = 0; d < 3; d++) {
        const float* gp = gi + ((long)(d*8192 + r))*384;
        float rr = sigmoidf_(gp[o]       + ghr);
        float zz = sigmoidf_(gp[128 + o] + ghz);
        float nn = tanhf    (gp[256 + o] + rr*ghn);
        acc += (1.0f - zz)*nn + zz*h;
    }
    float outv = fmaxf(acc, 0.0f);
    xout[idx] = outv*t + h*(1.0f - t);
}

// ---------------------------------------------------------------------------
extern "C" void kernel_launch(void* const* d_in, const int* in_sizes, int n_in,
                              void* d_out, int out_size)
{
    const float* inputs = (const float*)d_in[0];
    const float* adj    = (const float*)d_in[1];
    const float* W      = (const float*)d_in[2];
    const float* Bc     = (const float*)d_in[3];
    const float* Wh     = (const float*)d_in[4];
    const float* Bh     = (const float*)d_in[5];
    const float* Wih    = (const float*)d_in[6];
    const float* Whh    = (const float*)d_in[7];
    const float* bih    = (const float*)d_in[8];
    const float* bhh    = (const float*)d_in[9];
    float* out = (float*)d_out;
    (void)in_sizes; (void)n_in; (void)out_size;

    float *support, *supT, *agg, *gi, *ght, *xmid, *wTr, *whcatr, *wihr, *bcat;
    cudaGetSymbolAddress((void**)&support, g_support);
    cudaGetSymbolAddress((void**)&supT,    g_supT);
    cudaGetSymbolAddress((void**)&agg,     g_agg);
    cudaGetSymbolAddress((void**)&gi,      g_gi);
    cudaGetSymbolAddress((void**)&ght,     g_ght);
    cudaGetSymbolAddress((void**)&xmid,    g_x);
    cudaGetSymbolAddress((void**)&wTr,     g_wTr);
    cudaGetSymbolAddress((void**)&whcatr,  g_whcatr);
    cudaGetSymbolAddress((void**)&wihr,    g_wihr);
    cudaGetSymbolAddress((void**)&bcat,    g_bcat);

    cudaFuncSetAttribute(agg_mma_k, cudaFuncAttributeMaxDynamicSharedMemorySize,
                         AG_SMEM_BYTES);

    prep_weights<<<512, 256>>>(W, Whh, Wh, Wih, bhh, Bh, wTr, whcatr, wihr, bcat);

    for (int l = 0; l < 2; l++) {
        const float* xi = (l == 0) ? inputs : xmid;
        float*       xo = (l == 1) ? out    : xmid;

        // support = x @ W^T + Bc   (1x: B pre-rounded, A rounded at frag)
        mma_gemm_1x<<<dim3(64,1,3), 256>>>(
            xi, wTr + (long)l*DDIR*16384, Bc + l*DDIR*128, support,
            128, 128, 128, 128,
            0L, 16384L, 1,
            (long)NNODES*BB*OO, 0L, 128);

        // supT = transpose, pre-rounded to tf32 (B operand of agg)
        transpose_support<<<dim3(32,4,24), dim3(32,8)>>>(support, supT);

        // agg = adj @ support   (1x tf32, BK=16 4-stage cp.async, occ 2)
        agg_mma_k<<<dim3(8,24), 256, AG_SMEM_BYTES>>>(adj, supT, agg);

        // gi = agg @ Wih^T + bih   (1x)
        mma_gemm_1x<<<dim3(192,3,1), 256>>>(
            agg, wihr + (long)l*384*128, bih + l*384, gi,
            128, 128, 128, 384,
            0L, 0L, 1, 0L, 0L, 0);

        // ght = x @ [Whh | Wh^T]^T + [bhh | Bh]   (1x)
        mma_gemm_1x<<<dim3(64,4,1), 256>>>(
            xi, whcatr + (long)l*512*128, bcat + l*512, ght,
            128, 128, 128, 512,
            0L, 0L, 1, 0L, 0L, 0);

        gru_highway<<<4096, 256>>>(xi, ght, gi, xo);
    }
}